// round 16
// baseline (speedup 1.0000x reference)
#include <cuda_runtime.h>
#include <math.h>

#define BATCH 16
#define HH 512
#define WW 512
#define W4 (WW / 4)
#define WIN 15
#define RAD 7
#define SEG 28                 // output float4 columns per warp segment
#define GRX 5                  // ceil(128/28)
#define GRY 16                 // 512 rows / 32 (CTA = 2 warps x 16 rows)
#define NT 64
#define NBLOCKS (GRX * GRY * BATCH)   // 1280

__device__ double g_part[NBLOCKS][6];
__device__ unsigned int g_count = 0;

// Horizontal 15-tap window sums via prefix/suffix decomposition:
// W_i = sfx_{3-i}(l-2) + T(l-1)+T(l)+T(l+1) + pfx_i(l+2). 8 shuffles/array.
__device__ __forceinline__ void hwin(const float4 V, int lane,
                                     float& W0, float& W1, float& W2, float& W3) {
    const float pfx1 = V.x;
    const float pfx2 = V.x + V.y;
    const float pfx3 = pfx2 + V.z;
    const float T    = pfx3 + V.w;
    const float sfx1 = V.w;
    const float sfx2 = V.z + V.w;
    const float sfx3 = V.y + sfx2;

    const float s3 = __shfl_sync(0xFFFFFFFFu, sfx3, lane - 2);
    const float s2 = __shfl_sync(0xFFFFFFFFu, sfx2, lane - 2);
    const float s1 = __shfl_sync(0xFFFFFFFFu, sfx1, lane - 2);
    const float p1 = __shfl_sync(0xFFFFFFFFu, pfx1, lane + 2);
    const float p2 = __shfl_sync(0xFFFFFFFFu, pfx2, lane + 2);
    const float p3 = __shfl_sync(0xFFFFFFFFu, pfx3, lane + 2);
    const float Tm = __shfl_sync(0xFFFFFFFFu, T, lane - 1);
    const float Tp = __shfl_sync(0xFFFFFFFFu, T, lane + 1);

    const float base = Tm + T + Tp;
    W0 = base + s3;
    W1 = base + s2 + p1;
    W2 = base + s1 + p2;
    W3 = base + p3;
}

__device__ __forceinline__ void hstep(const float4 VI, const float4 VJ,
                                      bool own, int lane,
                                      float& sII, float& sJJ, float& sIJ) {
    float a0, a1, a2, a3, b0, b1, b2, b3;
    hwin(VI, lane, a0, a1, a2, a3);
    hwin(VJ, lane, b0, b1, b2, b3);
    if (own) {
        sII += a0 * a0 + a1 * a1 + a2 * a2 + a3 * a3;
        sJJ += b0 * b0 + b1 * b1 + b2 * b2 + b3 * b3;
        sIJ += a0 * b0 + a1 * b1 + a2 * b2 + a3 * b3;
    }
}

__global__ void __launch_bounds__(NT)
ncc_fused(const float* __restrict__ I, const float* __restrict__ J,
          float* __restrict__ out) {
    const int tid  = threadIdx.x;
    const int lane = tid & 31;
    const int wrp  = tid >> 5;
    const int bx = blockIdx.x, by = blockIdx.y, bz = blockIdx.z;

    const int c4     = bx * SEG - 2 + lane;          // float4 col with 2-halo
    const bool colok = (c4 >= 0) && (c4 < W4);
    const bool own   = (lane >= 2) && (lane < 2 + SEG) && (c4 < W4);
    const int cx = c4 * 4;

    float wx0 = 0.f, wx1 = 0.f, wx2 = 0.f, wx3 = 0.f;
    if (own) {
        wx0 = (float)(min(cx + 0 + RAD, WW - 1) - max(cx + 0 - RAD, 0) + 1);
        wx1 = (float)(min(cx + 1 + RAD, WW - 1) - max(cx + 1 - RAD, 0) + 1);
        wx2 = (float)(min(cx + 2 + RAD, WW - 1) - max(cx + 2 - RAD, 0) + 1);
        wx3 = (float)(min(cx + 3 + RAD, WW - 1) - max(cx + 3 - RAD, 0) + 1);
    }

    const float4* __restrict__ I4 = (const float4*)I + (size_t)bz * HH * W4;
    const float4* __restrict__ J4 = (const float4*)J + (size_t)bz * HH * W4;

    const int y0 = by * 32 + wrp * 16;               // warp's first output row
    const float4 zero = make_float4(0.f, 0.f, 0.f, 0.f);

    float4 VI = zero, VJ = zero;
    float pII = 0.f, pJJ = 0.f, pIJ = 0.f;
    float sII = 0.f, sJJ = 0.f, sIJ = 0.f;

    // ---- init vertical window rows y0-7 .. y0+7 (owned rows y0..y0+7) ----
    #pragma unroll
    for (int k = 0; k < WIN; k++) {
        const int gy = y0 - RAD + k;                 // <= 503 always
        float4 vi = zero, vj = zero;
        if (colok && gy >= 0) {
            vi = __ldg(I4 + gy * W4 + c4);
            vj = __ldg(J4 + gy * W4 + c4);
        }
        VI.x += vi.x; VI.y += vi.y; VI.z += vi.z; VI.w += vi.w;
        VJ.x += vj.x; VJ.y += vj.y; VJ.z += vj.z; VJ.w += vj.w;
        if (k >= RAD && own) {                       // owned pixel row gy
            const float wy = (float)(min(gy + RAD, HH - 1) - max(gy - RAD, 0) + 1);
            pII += wy * (wx0 * vi.x * vi.x + wx1 * vi.y * vi.y +
                         wx2 * vi.z * vi.z + wx3 * vi.w * vi.w);
            pJJ += wy * (wx0 * vj.x * vj.x + wx1 * vj.y * vj.y +
                         wx2 * vj.z * vj.z + wx3 * vj.w * vj.w);
            pIJ += wy * (wx0 * vi.x * vj.x + wx1 * vi.y * vj.y +
                         wx2 * vi.z * vj.z + wx3 * vi.w * vj.w);
        }
    }
    hstep(VI, VJ, own, lane, sII, sJJ, sIJ);         // output row y0

    // ---- slides: output rows y0+1 .. y0+15 ----
    // New row gyn = y0+8+j; owned new rows are j=0..7 (y0+8..y0+15, always
    // in-bounds since y0+15 <= 511). Their quadratics accumulate here.
    #pragma unroll
    for (int j = 0; j < 15; j++) {
        const int gyn = y0 + RAD + 1 + j;
        const int gyo = y0 - RAD + j;
        float4 ni = zero, nj = zero, oi = zero, oj = zero;
        if (colok && gyn < HH) {
            ni = __ldg(I4 + gyn * W4 + c4);
            nj = __ldg(J4 + gyn * W4 + c4);
        }
        if (colok && gyo >= 0) {
            oi = __ldg(I4 + gyo * W4 + c4);           // L1/L2 hit (recent)
            oj = __ldg(J4 + gyo * W4 + c4);
        }
        if (j < 8 && own) {                           // owned pixel row gyn
            const float wy = (float)(min(gyn + RAD, HH - 1) - max(gyn - RAD, 0) + 1);
            pII += wy * (wx0 * ni.x * ni.x + wx1 * ni.y * ni.y +
                         wx2 * ni.z * ni.z + wx3 * ni.w * ni.w);
            pJJ += wy * (wx0 * nj.x * nj.x + wx1 * nj.y * nj.y +
                         wx2 * nj.z * nj.z + wx3 * nj.w * nj.w);
            pIJ += wy * (wx0 * ni.x * nj.x + wx1 * ni.y * nj.y +
                         wx2 * ni.z * nj.z + wx3 * ni.w * nj.w);
        }
        VI.x += ni.x - oi.x; VI.y += ni.y - oi.y;
        VI.z += ni.z - oi.z; VI.w += ni.w - oi.w;
        VJ.x += nj.x - oj.x; VJ.y += nj.y - oj.y;
        VJ.z += nj.z - oj.z; VJ.w += nj.w - oj.w;
        hstep(VI, VJ, own, lane, sII, sJJ, sIJ);     // output row y0+1+j
    }

    // ---- reductions: float within warp, double across warps/CTAs ----
    float r0 = pII, r1 = pJJ, r2 = pIJ, r3 = sII, r4 = sJJ, r5 = sIJ;
    #pragma unroll
    for (int off = 16; off > 0; off >>= 1) {
        r0 += __shfl_xor_sync(0xFFFFFFFFu, r0, off);
        r1 += __shfl_xor_sync(0xFFFFFFFFu, r1, off);
        r2 += __shfl_xor_sync(0xFFFFFFFFu, r2, off);
        r3 += __shfl_xor_sync(0xFFFFFFFFu, r3, off);
        r4 += __shfl_xor_sync(0xFFFFFFFFu, r4, off);
        r5 += __shfl_xor_sync(0xFFFFFFFFu, r5, off);
    }
    __shared__ double red[NT / 32][6];
    if (lane == 0) {
        red[wrp][0] = (double)r0; red[wrp][1] = (double)r1; red[wrp][2] = (double)r2;
        red[wrp][3] = (double)r3; red[wrp][4] = (double)r4; red[wrp][5] = (double)r5;
    }
    __syncthreads();

    __shared__ int s_last;
    const int bid = bx + GRX * (by + GRY * bz);
    if (tid == 0) {
        double t0 = 0, t1 = 0, t2 = 0, t3 = 0, t4 = 0, t5 = 0;
        #pragma unroll
        for (int w = 0; w < NT / 32; w++) {
            t0 += red[w][0]; t1 += red[w][1]; t2 += red[w][2];
            t3 += red[w][3]; t4 += red[w][4]; t5 += red[w][5];
        }
        g_part[bid][0] = t0; g_part[bid][1] = t1; g_part[bid][2] = t2;
        g_part[bid][3] = t3; g_part[bid][4] = t4; g_part[bid][5] = t5;
        __threadfence();
        unsigned int prev = atomicAdd(&g_count, 1u);
        s_last = (prev == NBLOCKS - 1);
    }
    __syncthreads();

    // ---- last CTA: global reduce + finalize ----
    if (s_last) {
        double c0 = 0, c1 = 0, c2 = 0, c3 = 0, c4d = 0, c5 = 0;
        for (int c = tid; c < NBLOCKS; c += NT) {
            c0 += g_part[c][0]; c1 += g_part[c][1]; c2 += g_part[c][2];
            c3 += g_part[c][3]; c4d += g_part[c][4]; c5 += g_part[c][5];
        }
        __shared__ double red2[NT / 32][6];
        #pragma unroll
        for (int off = 16; off > 0; off >>= 1) {
            c0 += __shfl_xor_sync(0xFFFFFFFFu, c0, off);
            c1 += __shfl_xor_sync(0xFFFFFFFFu, c1, off);
            c2 += __shfl_xor_sync(0xFFFFFFFFu, c2, off);
            c3 += __shfl_xor_sync(0xFFFFFFFFu, c3, off);
            c4d += __shfl_xor_sync(0xFFFFFFFFu, c4d, off);
            c5 += __shfl_xor_sync(0xFFFFFFFFu, c5, off);
        }
        if (lane == 0) {
            red2[wrp][0] = c0; red2[wrp][1] = c1; red2[wrp][2] = c2;
            red2[wrp][3] = c3; red2[wrp][4] = c4d; red2[wrp][5] = c5;
        }
        __syncthreads();
        if (tid == 0) {
            double t0 = 0, t1 = 0, t2 = 0, t3 = 0, t4 = 0, t5 = 0;
            #pragma unroll
            for (int w = 0; w < NT / 32; w++) {
                t0 += red2[w][0]; t1 += red2[w][1]; t2 += red2[w][2];
                t3 += red2[w][3]; t4 += red2[w][4]; t5 += red2[w][5];
            }
            const double inv = 1.0 / 225.0;
            const double cross = t2 - t5 * inv;
            const double iv    = t0 - t3 * inv;
            const double jv    = t1 - t4 * inv;
            out[0] = (float)(-(cross / sqrt(iv * jv)));
            g_count = 0;   // reset for next graph replay
        }
    }
}

extern "C" void kernel_launch(void* const* d_in, const int* in_sizes, int n_in,
                              void* d_out, int out_size) {
    const float* I = (const float*)d_in[0];
    const float* J = (const float*)d_in[1];
    float* out = (float*)d_out;

    dim3 grid(GRX, GRY, BATCH);   // (5, 16, 16) = 1280 CTAs
    ncc_fused<<<grid, NT>>>(I, J, out);
}

// round 17
// speedup vs baseline: 1.0837x; 1.0837x over previous
#include <cuda_runtime.h>
#include <math.h>

#define BATCH 16
#define HH 512
#define WW 512
#define W4 (WW / 4)
#define WIN 15
#define RAD 7
#define SEG 28                 // output float4 columns per warp segment
#define GRX 5                  // ceil(128/28)
#define GRY 16                 // 512 rows / 32 (CTA = 4 warps x 8 rows)
#define NT 128
#define NBLOCKS (GRX * GRY * BATCH)   // 1280

__device__ double g_part[NBLOCKS][6];
__device__ unsigned int g_count = 0;

// Horizontal 15-tap window sums via prefix/suffix decomposition:
// W_i = sfx_{3-i}(l-2) + T(l-1)+T(l)+T(l+1) + pfx_i(l+2). 8 shuffles/array.
__device__ __forceinline__ void hwin(const float4 V, int lane,
                                     float& W0, float& W1, float& W2, float& W3) {
    const float pfx1 = V.x;
    const float pfx2 = V.x + V.y;
    const float pfx3 = pfx2 + V.z;
    const float T    = pfx3 + V.w;
    const float sfx1 = V.w;
    const float sfx2 = V.z + V.w;
    const float sfx3 = V.y + sfx2;

    const float s3 = __shfl_sync(0xFFFFFFFFu, sfx3, lane - 2);
    const float s2 = __shfl_sync(0xFFFFFFFFu, sfx2, lane - 2);
    const float s1 = __shfl_sync(0xFFFFFFFFu, sfx1, lane - 2);
    const float p1 = __shfl_sync(0xFFFFFFFFu, pfx1, lane + 2);
    const float p2 = __shfl_sync(0xFFFFFFFFu, pfx2, lane + 2);
    const float p3 = __shfl_sync(0xFFFFFFFFu, pfx3, lane + 2);
    const float Tm = __shfl_sync(0xFFFFFFFFu, T, lane - 1);
    const float Tp = __shfl_sync(0xFFFFFFFFu, T, lane + 1);

    const float base = Tm + T + Tp;
    W0 = base + s3;
    W1 = base + s2 + p1;
    W2 = base + s1 + p2;
    W3 = base + p3;
}

__device__ __forceinline__ void hstep(const float4 VI, const float4 VJ,
                                      bool own, int lane,
                                      float& sII, float& sJJ, float& sIJ) {
    float a0, a1, a2, a3, b0, b1, b2, b3;
    hwin(VI, lane, a0, a1, a2, a3);
    hwin(VJ, lane, b0, b1, b2, b3);
    if (own) {
        sII += a0 * a0 + a1 * a1 + a2 * a2 + a3 * a3;
        sJJ += b0 * b0 + b1 * b1 + b2 * b2 + b3 * b3;
        sIJ += a0 * b0 + a1 * b1 + a2 * b2 + a3 * b3;
    }
}

// Per-warp work: 8 output rows starting at y0. SAFE = all streamed rows
// (y0-7 .. y0+14) are in-bounds -> no row predicates at all.
template <bool SAFE>
__device__ __forceinline__ void warp_body(
    const float4* __restrict__ I4, const float4* __restrict__ J4,
    int y0, int c4, bool colok, bool own, int lane,
    float wx0, float wx1, float wx2, float wx3,
    float& pII, float& pJJ, float& pIJ,
    float& sII, float& sJJ, float& sIJ)
{
    const float4 zero = make_float4(0.f, 0.f, 0.f, 0.f);
    float4 VI = zero, VJ = zero;

    // ---- init vertical window rows y0-7 .. y0+7 (owned pixels at k>=7) ----
    #pragma unroll
    for (int k = 0; k < WIN; k++) {
        const int gy = y0 - RAD + k;
        float4 vi = zero, vj = zero;
        if (colok && (SAFE || gy >= 0)) {
            vi = __ldg(I4 + gy * W4 + c4);
            vj = __ldg(J4 + gy * W4 + c4);
        }
        VI.x += vi.x; VI.y += vi.y; VI.z += vi.z; VI.w += vi.w;
        VJ.x += vj.x; VJ.y += vj.y; VJ.z += vj.z; VJ.w += vj.w;
        if (k >= RAD && own) {
            const float wy = (float)(min(gy + RAD, HH - 1) - max(gy - RAD, 0) + 1);
            pII += wy * (wx0 * vi.x * vi.x + wx1 * vi.y * vi.y +
                         wx2 * vi.z * vi.z + wx3 * vi.w * vi.w);
            pJJ += wy * (wx0 * vj.x * vj.x + wx1 * vj.y * vj.y +
                         wx2 * vj.z * vj.z + wx3 * vj.w * vj.w);
            pIJ += wy * (wx0 * vi.x * vj.x + wx1 * vi.y * vj.y +
                         wx2 * vi.z * vj.z + wx3 * vi.w * vj.w);
        }
    }
    hstep(VI, VJ, own, lane, sII, sJJ, sIJ);         // output row y0

    // ---- slides: output rows y0+1 .. y0+7 ----
    #pragma unroll
    for (int j = 0; j < 7; j++) {
        const int gyn = y0 + RAD + 1 + j;
        const int gyo = y0 - RAD + j;
        float4 ni = zero, nj = zero, oi = zero, oj = zero;
        if (colok && (SAFE || gyn < HH)) {
            ni = __ldg(I4 + gyn * W4 + c4);
            nj = __ldg(J4 + gyn * W4 + c4);
        }
        if (colok && (SAFE || gyo >= 0)) {
            oi = __ldg(I4 + gyo * W4 + c4);           // L1/L2 hit (recent)
            oj = __ldg(J4 + gyo * W4 + c4);
        }
        VI.x += ni.x - oi.x; VI.y += ni.y - oi.y;
        VI.z += ni.z - oi.z; VI.w += ni.w - oi.w;
        VJ.x += nj.x - oj.x; VJ.y += nj.y - oj.y;
        VJ.z += nj.z - oj.z; VJ.w += nj.w - oj.w;
        hstep(VI, VJ, own, lane, sII, sJJ, sIJ);     // output row y0+1+j
    }
}

__global__ void __launch_bounds__(NT)
ncc_fused(const float* __restrict__ I, const float* __restrict__ J,
          float* __restrict__ out) {
    const int tid  = threadIdx.x;
    const int lane = tid & 31;
    const int wrp  = tid >> 5;
    const int bx = blockIdx.x, by = blockIdx.y, bz = blockIdx.z;

    const int c4     = bx * SEG - 2 + lane;          // float4 col with 2-halo
    const bool colok = (c4 >= 0) && (c4 < W4);
    const bool own   = (lane >= 2) && (lane < 2 + SEG) && (c4 < W4);
    const int cx = c4 * 4;

    float wx0 = 0.f, wx1 = 0.f, wx2 = 0.f, wx3 = 0.f;
    if (own) {
        wx0 = (float)(min(cx + 0 + RAD, WW - 1) - max(cx + 0 - RAD, 0) + 1);
        wx1 = (float)(min(cx + 1 + RAD, WW - 1) - max(cx + 1 - RAD, 0) + 1);
        wx2 = (float)(min(cx + 2 + RAD, WW - 1) - max(cx + 2 - RAD, 0) + 1);
        wx3 = (float)(min(cx + 3 + RAD, WW - 1) - max(cx + 3 - RAD, 0) + 1);
    }

    const float4* __restrict__ I4 = (const float4*)I + (size_t)bz * HH * W4;
    const float4* __restrict__ J4 = (const float4*)J + (size_t)bz * HH * W4;

    const int y0 = by * 32 + wrp * 8;                // warp's first output row

    float pII = 0.f, pJJ = 0.f, pIJ = 0.f;
    float sII = 0.f, sJJ = 0.f, sIJ = 0.f;

    // Uniform per-warp branch: rows y0-7 .. y0+14 all in-bounds for 62/64 warps.
    if (y0 >= RAD && y0 + 14 < HH) {
        warp_body<true>(I4, J4, y0, c4, colok, own, lane,
                        wx0, wx1, wx2, wx3, pII, pJJ, pIJ, sII, sJJ, sIJ);
    } else {
        warp_body<false>(I4, J4, y0, c4, colok, own, lane,
                         wx0, wx1, wx2, wx3, pII, pJJ, pIJ, sII, sJJ, sIJ);
    }

    // ---- reductions: float within warp, double across warps/CTAs ----
    float r0 = pII, r1 = pJJ, r2 = pIJ, r3 = sII, r4 = sJJ, r5 = sIJ;
    #pragma unroll
    for (int off = 16; off > 0; off >>= 1) {
        r0 += __shfl_xor_sync(0xFFFFFFFFu, r0, off);
        r1 += __shfl_xor_sync(0xFFFFFFFFu, r1, off);
        r2 += __shfl_xor_sync(0xFFFFFFFFu, r2, off);
        r3 += __shfl_xor_sync(0xFFFFFFFFu, r3, off);
        r4 += __shfl_xor_sync(0xFFFFFFFFu, r4, off);
        r5 += __shfl_xor_sync(0xFFFFFFFFu, r5, off);
    }
    __shared__ double red[NT / 32][6];
    if (lane == 0) {
        red[wrp][0] = (double)r0; red[wrp][1] = (double)r1; red[wrp][2] = (double)r2;
        red[wrp][3] = (double)r3; red[wrp][4] = (double)r4; red[wrp][5] = (double)r5;
    }
    __syncthreads();

    __shared__ int s_last;
    const int bid = bx + GRX * (by + GRY * bz);
    if (tid == 0) {
        double t0 = 0, t1 = 0, t2 = 0, t3 = 0, t4 = 0, t5 = 0;
        #pragma unroll
        for (int w = 0; w < NT / 32; w++) {
            t0 += red[w][0]; t1 += red[w][1]; t2 += red[w][2];
            t3 += red[w][3]; t4 += red[w][4]; t5 += red[w][5];
        }
        g_part[bid][0] = t0; g_part[bid][1] = t1; g_part[bid][2] = t2;
        g_part[bid][3] = t3; g_part[bid][4] = t4; g_part[bid][5] = t5;
        __threadfence();
        unsigned int prev = atomicAdd(&g_count, 1u);
        s_last = (prev == NBLOCKS - 1);
    }
    __syncthreads();

    // ---- last CTA: global reduce + finalize ----
    if (s_last) {
        double c0 = 0, c1 = 0, c2 = 0, c3 = 0, c4d = 0, c5 = 0;
        for (int c = tid; c < NBLOCKS; c += NT) {
            c0 += g_part[c][0]; c1 += g_part[c][1]; c2 += g_part[c][2];
            c3 += g_part[c][3]; c4d += g_part[c][4]; c5 += g_part[c][5];
        }
        __shared__ double red2[NT / 32][6];
        #pragma unroll
        for (int off = 16; off > 0; off >>= 1) {
            c0 += __shfl_xor_sync(0xFFFFFFFFu, c0, off);
            c1 += __shfl_xor_sync(0xFFFFFFFFu, c1, off);
            c2 += __shfl_xor_sync(0xFFFFFFFFu, c2, off);
            c3 += __shfl_xor_sync(0xFFFFFFFFu, c3, off);
            c4d += __shfl_xor_sync(0xFFFFFFFFu, c4d, off);
            c5 += __shfl_xor_sync(0xFFFFFFFFu, c5, off);
        }
        if (lane == 0) {
            red2[wrp][0] = c0; red2[wrp][1] = c1; red2[wrp][2] = c2;
            red2[wrp][3] = c3; red2[wrp][4] = c4d; red2[wrp][5] = c5;
        }
        __syncthreads();
        if (tid == 0) {
            double t0 = 0, t1 = 0, t2 = 0, t3 = 0, t4 = 0, t5 = 0;
            #pragma unroll
            for (int w = 0; w < NT / 32; w++) {
                t0 += red2[w][0]; t1 += red2[w][1]; t2 += red2[w][2];
                t3 += red2[w][3]; t4 += red2[w][4]; t5 += red2[w][5];
            }
            const double inv = 1.0 / 225.0;
            const double cross = t2 - t5 * inv;
            const double iv    = t0 - t3 * inv;
            const double jv    = t1 - t4 * inv;
            out[0] = (float)(-(cross / sqrt(iv * jv)));
            g_count = 0;   // reset for next graph replay
        }
    }
}

extern "C" void kernel_launch(void* const* d_in, const int* in_sizes, int n_in,
                              void* d_out, int out_size) {
    const float* I = (const float*)d_in[0];
    const float* J = (const float*)d_in[1];
    float* out = (float*)d_out;

    dim3 grid(GRX, GRY, BATCH);   // (5, 16, 16) = 1280 CTAs
    ncc_fused<<<grid, NT>>>(I, J, out);
}